// round 7
// baseline (speedup 1.0000x reference)
#include <cuda_runtime.h>

// LearnableDemosaick: per-pixel soft filter selection over K=8 5x5 filters.
// B=16, H=W=512. Only non-green (checkerboard) pixels need the conv+softmax;
// green pixels copy the mosaic. Packed f32x2 FMA doubles fp32 throughput.
// R5: filters back in smem (R2 path); pixel loads vectorized to LDS.128;
// launch_bounds(128,6) for occupancy.

#define Bn 16
#define Hd 512
#define Wd 512
#define TW 128   // output cols per block
#define TH 8     // output rows per block
#define NT 128   // threads per block (16 x-segments x 8 rows)

__device__ __forceinline__ unsigned long long ffma2(unsigned long long a,
                                                    unsigned long long b,
                                                    unsigned long long c) {
    unsigned long long d;
    asm("fma.rn.f32x2 %0, %1, %2, %3;" : "=l"(d) : "l"(a), "l"(b), "l"(c));
    return d;
}
__device__ __forceinline__ unsigned long long pk2(float lo, float hi) {
    unsigned long long r;
    asm("mov.b64 %0, {%1, %2};" : "=l"(r) : "f"(lo), "f"(hi));
    return r;
}
__device__ __forceinline__ void upk2(unsigned long long v, float& lo, float& hi) {
    asm("mov.b64 {%0, %1}, %2;" : "=f"(lo), "=f"(hi) : "l"(v));
}

__device__ __forceinline__ float softmax_combine(const float* s, const float* g) {
    float m = s[0];
    #pragma unroll
    for (int k = 1; k < 8; k++) m = fmaxf(m, s[k]);
    float den = 0.f, num = 0.f;
    #pragma unroll
    for (int k = 0; k < 8; k++) {
        float e = __expf(s[k] - m);
        den += e;
        num = fmaf(e, g[k], num);
    }
    return __fdividef(num, den);
}

__global__ void __launch_bounds__(NT, 6)
demosaick_kernel(const float* __restrict__ mosaick,
                 const float* __restrict__ selF,
                 const float* __restrict__ grnF,
                 float* __restrict__ out) {
    __shared__ __align__(16) float tile[TH + 4][TW + 4];   // 12 x 132 (row=528B)
    __shared__ __align__(16) float4 filt[200];             // [tap][k] = {s,s,g,g}

    const int tid = threadIdx.x;
    const int x0 = blockIdx.x * TW;
    const int y0 = blockIdx.y * TH;
    const size_t base = (size_t)blockIdx.z * Hd * Wd;

    // Filters, duplicated for packed FMA broadcast. Layout [f,f,K] -> flat i.
    for (int i = tid; i < 200; i += NT) {
        float s = selF[i], g = grnF[i];
        filt[i] = make_float4(s, s, g, g);
    }
    // Input tile with edge clamp (Halide clamp semantics).
    #pragma unroll
    for (int r = 0; r < TH + 4; r++) {
        int gy = y0 + r - 2;
        gy = gy < 0 ? 0 : (gy > Hd - 1 ? Hd - 1 : gy);
        for (int c = tid; c < TW + 4; c += NT) {
            int gx = x0 + c - 2;
            gx = gx < 0 ? 0 : (gx > Wd - 1 ? Wd - 1 : gx);
            tile[r][c] = mosaick[base + (size_t)gy * Wd + gx];
        }
    }
    __syncthreads();

    const int ty  = tid >> 4;         // row within tile
    const int txc = (tid & 15) * 8;   // output col base within tile
    const int y   = y0 + ty;          // global row
    const int p0  = (y + 1) & 1;      // non-green column parity for this row

    const ulonglong2* __restrict__ fsm = reinterpret_cast<const ulonglong2*>(filt);

    // 4 conv pixels per thread: pair A = cols (p0, p0+2), pair B = (p0+4, p0+6).
    unsigned long long sA[8], sB[8], gA[8], gB[8];
    #pragma unroll
    for (int k = 0; k < 8; k++) { sA[k] = 0ull; sB[k] = 0ull; gA[k] = 0ull; gB[k] = 0ull; }

    float gr[4];  // green copies, captured at dy==2 from the vector registers

    #pragma unroll
    for (int dy = 0; dy < 5; dy++) {
        const float* xr = &tile[ty + dy][txc];
        // 12 contiguous floats via 3 aligned LDS.128: covers cols txc..txc+11.
        float4 v0 = *reinterpret_cast<const float4*>(xr);
        float4 v1 = *reinterpret_cast<const float4*>(xr + 4);
        float4 v2 = *reinterpret_cast<const float4*>(xr + 8);
        float f[12] = {v0.x, v0.y, v0.z, v0.w, v1.x, v1.y, v1.z, v1.w,
                       v2.x, v2.y, v2.z, v2.w};
        // xi[i] = tile[row][txc + p0 + i], i = 0..10
        float xi[11];
        #pragma unroll
        for (int i = 0; i < 11; i++) xi[i] = p0 ? f[i + 1] : f[i];

        if (dy == 2) {
            // green cols: txc + (1-p0) + 2j + 2  ->  f[(p0 ? 2 : 3) + 2j]
            #pragma unroll
            for (int j = 0; j < 4; j++) gr[j] = p0 ? f[2 + 2 * j] : f[3 + 2 * j];
        }

        #pragma unroll
        for (int d = 0; d < 5; d++) {
            unsigned long long a = pk2(xi[d],     xi[d + 2]);
            unsigned long long b = pk2(xi[d + 4], xi[d + 6]);
            #pragma unroll
            for (int k = 0; k < 8; k++) {
                ulonglong2 fq = fsm[(dy * 5 + d) * 8 + k];   // {s,s} , {g,g}
                sA[k] = ffma2(a, fq.x, sA[k]);
                gA[k] = ffma2(a, fq.y, gA[k]);
                sB[k] = ffma2(b, fq.x, sB[k]);
                gB[k] = ffma2(b, fq.y, gB[k]);
            }
        }
    }

    // Epilogue: softmax-combine the 4 conv pixels.
    float cv[4];
    {
        float s0[8], s1[8], g0[8], g1[8];
        #pragma unroll
        for (int k = 0; k < 8; k++) { upk2(sA[k], s0[k], s1[k]); upk2(gA[k], g0[k], g1[k]); }
        cv[0] = softmax_combine(s0, g0);
        cv[1] = softmax_combine(s1, g1);
        #pragma unroll
        for (int k = 0; k < 8; k++) { upk2(sB[k], s0[k], s1[k]); upk2(gB[k], g0[k], g1[k]); }
        cv[2] = softmax_combine(s0, g0);
        cv[3] = softmax_combine(s1, g1);
    }

    // Interleave per parity (static indices only -> stays in registers).
    float o[8];
    #pragma unroll
    for (int j = 0; j < 4; j++) {
        o[2 * j]     = p0 ? gr[j] : cv[j];
        o[2 * j + 1] = p0 ? cv[j] : gr[j];
    }

    float4* op = reinterpret_cast<float4*>(out + base + (size_t)y * Wd + x0 + txc);
    op[0] = make_float4(o[0], o[1], o[2], o[3]);
    op[1] = make_float4(o[4], o[5], o[6], o[7]);
}

extern "C" void kernel_launch(void* const* d_in, const int* in_sizes, int n_in,
                              void* d_out, int out_size) {
    const float* mosaick = (const float*)d_in[0];   // [16,1,512,512]
    const float* selF    = (const float*)d_in[1];   // [5,5,8]
    const float* grnF    = (const float*)d_in[2];   // [5,5,8]
    float* out           = (float*)d_out;           // [16,1,512,512]
    dim3 grid(Wd / TW, Hd / TH, Bn);                // (4, 64, 16)
    demosaick_kernel<<<grid, NT>>>(mosaick, selF, grnF, out);
}

// round 8
// speedup vs baseline: 1.9566x; 1.9566x over previous
#include <cuda_runtime.h>

// LearnableDemosaick: per-pixel soft filter selection over K=8 5x5 filters.
// B=16, H=W=512. Only non-green (checkerboard) pixels need the conv+softmax;
// green pixels copy the mosaic. Packed f32x2 FMA doubles fp32 throughput.
// R7: filters in __constant__ bank (dedicated const port, off the smem
// crossbar + LSU). Prep kernel packs {s,s}/{g,g} u64 pairs -> staging global,
// async D2D memcpy into the constant symbol (graph-capturable nodes).

#define Bn 16
#define Hd 512
#define Wd 512
#define TW 128   // output cols per block
#define TH 8     // output rows per block
#define NT 128   // threads per block (16 x-segments x 8 rows)

struct QPair { unsigned long long s, g; };  // {s,s} and {g,g} packed f32x2

__constant__ QPair c_quad[200];
__device__   QPair g_stage[200];

__global__ void prep_filters(const float* __restrict__ selF,
                             const float* __restrict__ grnF) {
    int i = threadIdx.x;
    if (i < 200) {
        float s = selF[i], g = grnF[i];
        unsigned long long ss, gg;
        asm("mov.b64 %0, {%1, %1};" : "=l"(ss) : "f"(s));
        asm("mov.b64 %0, {%1, %1};" : "=l"(gg) : "f"(g));
        g_stage[i].s = ss;
        g_stage[i].g = gg;
    }
}

__device__ __forceinline__ unsigned long long ffma2(unsigned long long a,
                                                    unsigned long long b,
                                                    unsigned long long c) {
    unsigned long long d;
    asm("fma.rn.f32x2 %0, %1, %2, %3;" : "=l"(d) : "l"(a), "l"(b), "l"(c));
    return d;
}
__device__ __forceinline__ unsigned long long pk2(float lo, float hi) {
    unsigned long long r;
    asm("mov.b64 %0, {%1, %2};" : "=l"(r) : "f"(lo), "f"(hi));
    return r;
}
__device__ __forceinline__ void upk2(unsigned long long v, float& lo, float& hi) {
    asm("mov.b64 {%0, %1}, %2;" : "=f"(lo), "=f"(hi) : "l"(v));
}

__device__ __forceinline__ float softmax_combine(const float* s, const float* g) {
    float m = s[0];
    #pragma unroll
    for (int k = 1; k < 8; k++) m = fmaxf(m, s[k]);
    float den = 0.f, num = 0.f;
    #pragma unroll
    for (int k = 0; k < 8; k++) {
        float e = __expf(s[k] - m);
        den += e;
        num = fmaf(e, g[k], num);
    }
    return __fdividef(num, den);
}

__global__ void __launch_bounds__(NT)
demosaick_kernel(const float* __restrict__ mosaick,
                 float* __restrict__ out) {
    __shared__ float tile[TH + 4][TW + 4];   // 12 x 132

    const int tid = threadIdx.x;
    const int x0 = blockIdx.x * TW;
    const int y0 = blockIdx.y * TH;
    const size_t base = (size_t)blockIdx.z * Hd * Wd;

    // Input tile with edge clamp (Halide clamp semantics).
    #pragma unroll
    for (int r = 0; r < TH + 4; r++) {
        int gy = y0 + r - 2;
        gy = gy < 0 ? 0 : (gy > Hd - 1 ? Hd - 1 : gy);
        for (int c = tid; c < TW + 4; c += NT) {
            int gx = x0 + c - 2;
            gx = gx < 0 ? 0 : (gx > Wd - 1 ? Wd - 1 : gx);
            tile[r][c] = mosaick[base + (size_t)gy * Wd + gx];
        }
    }
    __syncthreads();

    const int ty  = tid >> 4;         // row within tile
    const int txc = (tid & 15) * 8;   // output col base within tile
    const int y   = y0 + ty;          // global row
    const int p0  = (y + 1) & 1;      // non-green column parity for this row
    const int q0  = 1 - p0;           // green column parity

    // 4 conv pixels per thread: pair A = cols (p0, p0+2), pair B = (p0+4, p0+6).
    unsigned long long sA[8], sB[8], gA[8], gB[8];
    #pragma unroll
    for (int k = 0; k < 8; k++) { sA[k] = 0ull; sB[k] = 0ull; gA[k] = 0ull; gB[k] = 0ull; }

    #pragma unroll
    for (int dy = 0; dy < 5; dy++) {
        const float* xr = &tile[ty + dy][txc + p0];  // xi[i] = input at pixel0 col -2 + i
        float xi[11];
        #pragma unroll
        for (int i = 0; i < 11; i++) xi[i] = xr[i];
        #pragma unroll
        for (int d = 0; d < 5; d++) {
            const unsigned long long a = pk2(xi[d],     xi[d + 2]);
            const unsigned long long b = pk2(xi[d + 4], xi[d + 6]);
            #pragma unroll
            for (int k = 0; k < 8; k++) {
                const QPair fq = c_quad[(dy * 5 + d) * 8 + k];  // const bank, uniform
                sA[k] = ffma2(a, fq.s, sA[k]);
                gA[k] = ffma2(a, fq.g, gA[k]);
                sB[k] = ffma2(b, fq.s, sB[k]);
                gB[k] = ffma2(b, fq.g, gB[k]);
            }
        }
    }

    // Epilogue: softmax-combine the 4 conv pixels; copy the 4 green pixels.
    float cv[4];
    {
        float s0[8], s1[8], g0[8], g1[8];
        #pragma unroll
        for (int k = 0; k < 8; k++) { upk2(sA[k], s0[k], s1[k]); upk2(gA[k], g0[k], g1[k]); }
        cv[0] = softmax_combine(s0, g0);
        cv[1] = softmax_combine(s1, g1);
        #pragma unroll
        for (int k = 0; k < 8; k++) { upk2(sB[k], s0[k], s1[k]); upk2(gB[k], g0[k], g1[k]); }
        cv[2] = softmax_combine(s0, g0);
        cv[3] = softmax_combine(s1, g1);
    }
    float gr[4];
    #pragma unroll
    for (int j = 0; j < 4; j++) gr[j] = tile[ty + 2][txc + q0 + 2 * j + 2];

    // Interleave per parity (static indices only -> stays in registers).
    float o[8];
    #pragma unroll
    for (int j = 0; j < 4; j++) {
        o[2 * j]     = p0 ? gr[j] : cv[j];
        o[2 * j + 1] = p0 ? cv[j] : gr[j];
    }

    float4* op = reinterpret_cast<float4*>(out + base + (size_t)y * Wd + x0 + txc);
    op[0] = make_float4(o[0], o[1], o[2], o[3]);
    op[1] = make_float4(o[4], o[5], o[6], o[7]);
}

extern "C" void kernel_launch(void* const* d_in, const int* in_sizes, int n_in,
                              void* d_out, int out_size) {
    const float* mosaick = (const float*)d_in[0];   // [16,1,512,512]
    const float* selF    = (const float*)d_in[1];   // [5,5,8]
    const float* grnF    = (const float*)d_in[2];   // [5,5,8]
    float* out           = (float*)d_out;           // [16,1,512,512]

    prep_filters<<<1, 256>>>(selF, grnF);

    void *dst = nullptr, *src = nullptr;
    cudaGetSymbolAddress(&dst, c_quad);
    cudaGetSymbolAddress(&src, g_stage);
    cudaMemcpyAsync(dst, src, 200 * sizeof(QPair), cudaMemcpyDeviceToDevice);

    dim3 grid(Wd / TW, Hd / TH, Bn);                // (4, 64, 16)
    demosaick_kernel<<<grid, NT>>>(mosaick, out);
}

// round 11
// speedup vs baseline: 2.2228x; 1.1360x over previous
#include <cuda_runtime.h>

// LearnableDemosaick: per-pixel soft filter selection over K=8 5x5 filters.
// B=16, H=W=512. Only non-green (checkerboard) pixels need the conv+softmax;
// green pixels copy the mosaic. Packed f32x2 FMA doubles fp32 throughput.
// R7: filters in __constant__ bank. R8/R10: 2 conv pixels/thread @ 256
// threads (16 u64 accumulators -> ~half the registers -> ~2x occupancy).

#define Bn 16
#define Hd 512
#define Wd 512
#define TW 128   // output cols per block
#define TH 8     // output rows per block
#define NT 256   // threads per block (32 x-segments x 8 rows)

struct QPair { unsigned long long s, g; };  // {s,s} and {g,g} packed f32x2

__constant__ QPair c_quad[200];
__device__   QPair g_stage[200];

__global__ void prep_filters(const float* __restrict__ selF,
                             const float* __restrict__ grnF) {
    int i = threadIdx.x;
    if (i < 200) {
        float s = selF[i], g = grnF[i];
        unsigned long long ss, gg;
        asm("mov.b64 %0, {%1, %1};" : "=l"(ss) : "f"(s));
        asm("mov.b64 %0, {%1, %1};" : "=l"(gg) : "f"(g));
        g_stage[i].s = ss;
        g_stage[i].g = gg;
    }
}

__device__ __forceinline__ unsigned long long ffma2(unsigned long long a,
                                                    unsigned long long b,
                                                    unsigned long long c) {
    unsigned long long d;
    asm("fma.rn.f32x2 %0, %1, %2, %3;" : "=l"(d) : "l"(a), "l"(b), "l"(c));
    return d;
}
__device__ __forceinline__ unsigned long long pk2(float lo, float hi) {
    unsigned long long r;
    asm("mov.b64 %0, {%1, %2};" : "=l"(r) : "f"(lo), "f"(hi));
    return r;
}
__device__ __forceinline__ void upk2(unsigned long long v, float& lo, float& hi) {
    asm("mov.b64 {%0, %1}, %2;" : "=f"(lo), "=f"(hi) : "l"(v));
}

__device__ __forceinline__ float softmax_combine(const float* s, const float* g) {
    float m = s[0];
    #pragma unroll
    for (int k = 1; k < 8; k++) m = fmaxf(m, s[k]);
    float den = 0.f, num = 0.f;
    #pragma unroll
    for (int k = 0; k < 8; k++) {
        float e = __expf(s[k] - m);
        den += e;
        num = fmaf(e, g[k], num);
    }
    return __fdividef(num, den);
}

__global__ void __launch_bounds__(NT)
demosaick_kernel(const float* __restrict__ mosaick,
                 float* __restrict__ out) {
    __shared__ float tile[TH + 4][TW + 4];   // 12 x 132

    const int tid = threadIdx.x;
    const int x0 = blockIdx.x * TW;
    const int y0 = blockIdx.y * TH;
    const size_t base = (size_t)blockIdx.z * Hd * Wd;

    // Input tile with edge clamp (Halide clamp semantics). Flattened: 1584 elems.
    for (int i = tid; i < (TH + 4) * (TW + 4); i += NT) {
        int r = i / (TW + 4);
        int c = i - r * (TW + 4);
        int gy = y0 + r - 2;
        gy = gy < 0 ? 0 : (gy > Hd - 1 ? Hd - 1 : gy);
        int gx = x0 + c - 2;
        gx = gx < 0 ? 0 : (gx > Wd - 1 ? Wd - 1 : gx);
        tile[r][c] = mosaick[base + (size_t)gy * Wd + gx];
    }
    __syncthreads();

    const int ty  = tid >> 5;         // row within tile (0..7)
    const int txs = (tid & 31) * 4;   // output col base within tile (4-wide)
    const int y   = y0 + ty;          // global row
    const int p0  = (y + 1) & 1;      // non-green column parity for this row
    const int q0  = 1 - p0;           // green column parity

    // 2 conv pixels per thread: cols (txs+p0, txs+p0+2) as one f32x2 pair.
    unsigned long long sA[8], gA[8];
    #pragma unroll
    for (int k = 0; k < 8; k++) { sA[k] = 0ull; gA[k] = 0ull; }

    #pragma unroll
    for (int dy = 0; dy < 5; dy++) {
        // Taps for pixel cols (txs+p0, txs+p0+2) span tile cols txs+p0-2 .. txs+p0+4.
        // Tile col index of pixel0 is txs+p0+2 (x -> x - x0 + 2), so taps are
        // tile[ty+dy][txs+p0 .. txs+p0+6]; xi[i] = tile[ty+dy][txs+p0+i].
        const float* xr = &tile[ty + dy][txs + p0];
        float xi[7];
        #pragma unroll
        for (int i = 0; i < 7; i++) xi[i] = xr[i];
        #pragma unroll
        for (int d = 0; d < 5; d++) {
            const unsigned long long a = pk2(xi[d], xi[d + 2]);
            #pragma unroll
            for (int k = 0; k < 8; k++) {
                const QPair fq = c_quad[(dy * 5 + d) * 8 + k];  // const bank, uniform
                sA[k] = ffma2(a, fq.s, sA[k]);
                gA[k] = ffma2(a, fq.g, gA[k]);
            }
        }
    }

    // Epilogue: softmax-combine the 2 conv pixels; copy the 2 green pixels.
    float cv[2];
    {
        float s0[8], s1[8], g0[8], g1[8];
        #pragma unroll
        for (int k = 0; k < 8; k++) { upk2(sA[k], s0[k], s1[k]); upk2(gA[k], g0[k], g1[k]); }
        cv[0] = softmax_combine(s0, g0);
        cv[1] = softmax_combine(s1, g1);
    }
    float gr[2];
    #pragma unroll
    for (int j = 0; j < 2; j++) gr[j] = tile[ty + 2][txs + q0 + 2 * j + 2];

    // Interleave per parity (static indices only -> stays in registers).
    float o[4];
    #pragma unroll
    for (int j = 0; j < 2; j++) {
        o[2 * j]     = p0 ? gr[j] : cv[j];
        o[2 * j + 1] = p0 ? cv[j] : gr[j];
    }

    *reinterpret_cast<float4*>(out + base + (size_t)y * Wd + x0 + txs) =
        make_float4(o[0], o[1], o[2], o[3]);
}

extern "C" void kernel_launch(void* const* d_in, const int* in_sizes, int n_in,
                              void* d_out, int out_size) {
    const float* mosaick = (const float*)d_in[0];   // [16,1,512,512]
    const float* selF    = (const float*)d_in[1];   // [5,5,8]
    const float* grnF    = (const float*)d_in[2];   // [5,5,8]
    float* out           = (float*)d_out;           // [16,1,512,512]

    prep_filters<<<1, 256>>>(selF, grnF);

    void *dst = nullptr, *src = nullptr;
    cudaGetSymbolAddress(&dst, c_quad);
    cudaGetSymbolAddress(&src, g_stage);
    cudaMemcpyAsync(dst, src, 200 * sizeof(QPair), cudaMemcpyDeviceToDevice);

    dim3 grid(Wd / TW, Hd / TH, Bn);                // (4, 64, 16)
    demosaick_kernel<<<grid, NT>>>(mosaick, out);
}